// round 15
// baseline (speedup 1.0000x reference)
#include <cuda_runtime.h>
#include <stdint.h>

#define NSTAGE 4
#define CH_U2 2048u      // one 16KB chunk: [2 kt][32 nt][32 lane] uint2 (fp16 b-frags, k32 slab)
#define CH_BYTES 16384u

// dynamic smem layout (bytes)
// mbars: full[4] @ 0..64, empty[4] @ 64..128
#define OFF_T 128u                               // t_range 25 f32
#define OFF_BW 384u                              // float2 (b1, wt)[256] -> 2048B
#define OFF_B2 2432u                             // f32 b2[256] -> 1024B
#define OFF_Z 3584u                              // 128x256 fp16, comp-major tiles = 65536B
#define OFF_H (OFF_Z + 65536u)                   // 69120
#define OFF_RING (OFF_H + 65536u)                // 134656
#define DYN_SMEM (OFF_RING + NSTAGE * CH_BYTES)  // 200192

// prep output: 16 chunks (W1 k32-slabs 0-7, W2 k32-slabs 8-15) of 16KB fp16 b-frag images
__device__ __align__(128) uint2 g_wblk[16 * CH_U2];
// fp32 z master, c-fragment-coalesced: [128 cta][16 warp][16 q][32 lane] float4 = 16MB
__device__ __align__(16) float4 g_z[128 * 16 * 16 * 32];

// ---------- helpers ----------
__device__ __forceinline__ uint32_t smem_u32(const void* p) {
    uint32_t a;
    asm("{ .reg .u64 t; cvta.to.shared.u64 t, %1; cvt.u32.u64 %0, t; }" : "=r"(a) : "l"(p));
    return a;
}
// pack two f32 -> f16x2 (lo = first arg, hi = second), round-to-nearest
__device__ __forceinline__ uint32_t pack_h2(float lo, float hi) {
    uint32_t r;
    asm("cvt.rn.f16x2.f32 %0, %1, %2;" : "=r"(r) : "f"(hi), "f"(lo));
    return r;
}
// packed fp16x2 tanh (1 MUFU op for 2 values)
__device__ __forceinline__ uint32_t tanh_h2(uint32_t x) {
    uint32_t r;
    asm("tanh.approx.f16x2 %0, %1;" : "=r"(r) : "r"(x));
    return r;
}

#define MBINIT(addr, cnt) \
    asm volatile("mbarrier.init.shared.b64 [%0], %1;" :: "r"(addr), "r"(cnt) : "memory")
#define MB_TX(addr, bytes) \
    asm volatile("mbarrier.arrive.expect_tx.shared.b64 _, [%0], %1;" :: "r"(addr), "r"(bytes) : "memory")
#define MB_ARRIVE(addr) \
    asm volatile("mbarrier.arrive.shared.b64 _, [%0];" :: "r"(addr) : "memory")

#define WAITP(addr, par) do { \
    uint32_t _m = (addr), _p = (par), _d; \
    asm volatile("{\n\t.reg .pred p;\n\t" \
        "mbarrier.try_wait.parity.acquire.cta.shared::cta.b64 p, [%1], %2;\n\t" \
        "selp.b32 %0, 1, 0, p;\n\t}" : "=r"(_d) : "r"(_m), "r"(_p) : "memory"); \
    if (!_d) { \
        asm volatile("{\n\t.reg .pred P1;\n\t" \
            "WL_%=:\n\t" \
            "mbarrier.try_wait.parity.acquire.cta.shared::cta.b64 P1, [%0], %1, 0x989680;\n\t" \
            "@P1 bra.uni WD_%=;\n\tbra.uni WL_%=;\n\tWD_%=:\n\t}" \
            :: "r"(_m), "r"(_p) : "memory"); \
    } \
} while (0)

#define WAITPR(addr, par) do { \
    uint32_t _m = (addr), _p = (par), _d; \
    asm volatile("{\n\t.reg .pred p;\n\t" \
        "mbarrier.try_wait.parity.relaxed.cta.shared::cta.b64 p, [%1], %2, 0x989680;\n\t" \
        "selp.b32 %0, 1, 0, p;\n\t}" : "=r"(_d) : "r"(_m), "r"(_p) : "memory"); \
    if (!_d) { \
        asm volatile("{\n\t.reg .pred P1;\n\t" \
            "WL_%=:\n\t" \
            "mbarrier.try_wait.parity.relaxed.cta.shared::cta.b64 P1, [%0], %1, 0x989680;\n\t" \
            "@P1 bra.uni WD_%=;\n\tbra.uni WL_%=;\n\tWD_%=:\n\t}" \
            :: "r"(_m), "r"(_p) : "memory"); \
    } \
} while (0)

#define BAR1() asm volatile("bar.sync 1, 512;" ::: "memory")

__device__ __forceinline__ void bulk_g2s(uint32_t dst, const void* src, uint32_t bytes, uint32_t mbar) {
    asm volatile(
        "cp.async.bulk.shared::cluster.global.mbarrier::complete_tx::bytes [%0], [%1], %2, [%3];"
        :: "r"(dst), "l"(src), "r"(bytes), "r"(mbar) : "memory");
}

// mma.sync m16n8k16 f16->f32 (g=lane>>2, t=lane&3):
// a0=(g,2t:2t+1) a1=(g+8,2t:2t+1) a2=(g,2t+8:2t+9) a3=(g+8,2t+8:2t+9)  [lo = even k]
// b0=(2t:2t+1, g) b1=(2t+8:2t+9, g)                                     [lo = even k]
// c0=(g,2t) c1=(g,2t+1) c2=(g+8,2t) c3=(g+8,2t+1)
#define MMA16(d, ax, ay, az, aw, bx, by) \
    asm volatile("mma.sync.aligned.m16n8k16.row.col.f32.f16.f16.f32 " \
        "{%0,%1,%2,%3}, {%4,%5,%6,%7}, {%8,%9}, {%0,%1,%2,%3};" \
        : "+f"((d)[0]), "+f"((d)[1]), "+f"((d)[2]), "+f"((d)[3]) \
        : "r"(ax), "r"(ay), "r"(az), "r"(aw), "r"(bx), "r"(by))

// comp-major A-fragment layout: matrix (row 0..127, colpair 0..127) in 16x8cp tiles,
// tile T = (row>>4)*16 + (cp>>3); word = T*128 + comp*32 + lane,
// comp = ((row>>3)&1) + (((cp>>2)&1)<<1), lane = ((row&7)<<2) + (cp&3).
// Epilogue stores hit word == c*32 + own-lane -> conflict-free STS.32.
__device__ __forceinline__ void zh_store_pair(uint32_t* ZB, int row, int cp, uint32_t v) {
    int tile = ((row >> 4) << 4) + (cp >> 3);
    int comp = ((row >> 3) & 1) + (((cp >> 2) & 1) << 1);
    int ln = ((row & 7) << 2) + (cp & 3);
    ZB[tile * 128 + comp * 32 + ln] = v;
}

// ---------- prep: fp16-round + B-frag k32-slab images ----------
// chunk c = mat*8 + slab: B[k][n] = W[k][n], k in [slab*32,+32), n in [0,256)
// uint2 at ((kt*32 + nt)*32 + lane): b0 = {W[kb+2t][n], W[kb+2t+1][n]},
// b1 = {W[kb+2t+8][n], W[kb+2t+9][n]}, kb = slab*32 + kt*16, n = nt*8 + g
extern "C" __global__ void __launch_bounds__(256) ode_prep(
    const float* __restrict__ W1, const float* __restrict__ W2) {
    int c = blockIdx.x, mat = c >> 3, slab = c & 7;
    const float* W = mat ? W2 : W1;
    for (int e = threadIdx.x; e < (int)CH_U2; e += 256) {
        int lane = e & 31, nt = (e >> 5) & 31, kt = e >> 10;
        int g = lane >> 2, t = lane & 3;
        int kb = slab * 32 + kt * 16, n = nt * 8 + g;
        uint2 v;
        v.x = pack_h2(W[(kb + 2 * t) * 256 + n], W[(kb + 2 * t + 1) * 256 + n]);
        v.y = pack_h2(W[(kb + 2 * t + 8) * 256 + n], W[(kb + 2 * t + 9) * 256 + n]);
        g_wblk[c * CH_U2 + e] = v;
    }
}

// ---------- GEMM pass: D[32x64 per warp] += A(src buf) @ B(ring), k=256 over 8 k32 chunks ----------
__device__ __forceinline__ void gemm_pass(
    float (&d)[2][8][4], const char* smem, uint32_t sb, uint32_t a_off,
    int mi, int ni, int lane, uint32_t& cs, uint32_t& cp) {
    const uint32_t* A = (const uint32_t*)(smem + a_off);
    for (int kc = 0; kc < 8; kc++) {
        WAITP(sb + 16u * cs, cp);
        const uint2* Bk = (const uint2*)(smem + OFF_RING + cs * CH_BYTES);
#pragma unroll
        for (int kt = 0; kt < 2; kt++) {
            const int ktile = kc * 2 + kt;
            uint32_t a[2][4];
#pragma unroll
            for (int i = 0; i < 2; i++) {
                const uint32_t* Ab = A + (((mi * 2 + i) * 16 + ktile) * 128) + lane;
                a[i][0] = Ab[0]; a[i][1] = Ab[32]; a[i][2] = Ab[64]; a[i][3] = Ab[96];
            }
            uint2 b[8];
#pragma unroll
            for (int j = 0; j < 8; j++) b[j] = Bk[(kt * 32 + ni * 8 + j) * 32 + lane];
#pragma unroll
            for (int i = 0; i < 2; i++)
#pragma unroll
                for (int j = 0; j < 8; j++)
                    MMA16(d[i][j], a[i][0], a[i][1], a[i][2], a[i][3], b[j].x, b[j].y);
        }
        if (lane == 0) MB_ARRIVE(sb + 64u + 16u * cs);
        cs++; if (cs == NSTAGE) { cs = 0; cp ^= 1; }
    }
}

// ---------- main persistent kernel ----------
// 128 CTAs x 128 rows; warps 0-15 compute (4x4 grid of 32x64 tiles), warp 16 = producer.
// fp32 z master lives in g_z (fragment-coalesced); out written only at the last step.
extern "C" __global__ void __launch_bounds__(544, 1) ode_main(
    const float* __restrict__ z0, const float* __restrict__ t_range,
    const float* __restrict__ b1, const float* __restrict__ wt,
    const float* __restrict__ b2, float* __restrict__ out) {
    extern __shared__ char smem[];
    const uint32_t sb = smem_u32(smem);
    const int tid = threadIdx.x, w = tid >> 5, lane = tid & 31;
    const int row0 = blockIdx.x * 128;

    uint32_t* ZB = (uint32_t*)(smem + OFF_Z);
    uint32_t* HB = (uint32_t*)(smem + OFF_H);
    float* sT = (float*)(smem + OFF_T);
    float2* sBW = (float2*)(smem + OFF_BW);
    float* sB2 = (float*)(smem + OFF_B2);

    const int mi = w >> 2, ni = w & 3;  // warp tile: rows [mi*32,+32), cols [ni*64,+64)
    const int gid = lane >> 2, tig = lane & 3;

    if (tid == 0) {
        for (int s = 0; s < NSTAGE; s++) {
            MBINIT(sb + 16u * s, 1);         // full: producer MB_TX(1 arrive) + bulk bytes
            MBINIT(sb + 64u + 16u * s, 16);  // empty: one arrive per compute warp
        }
    }
    if (tid < 256) {
        sB2[tid] = b2[tid];
        sBW[tid] = make_float2(b1[tid], wt[tid]);
        if (tid < 25) sT[tid] = t_range[tid];
    }
    // per-warp init: gather z0 fragments -> g_z (coalesced) + fp16 image -> Z
    float4* zptr = g_z + (((size_t)blockIdx.x * 16 + w) * 16) * 32 + lane;
    if (w < 16) {
#pragma unroll
        for (int i = 0; i < 2; i++)
#pragma unroll
            for (int j = 0; j < 8; j++) {
                const int row = mi * 32 + i * 16 + gid;
                const int col = ni * 64 + j * 8 + 2 * tig;
                const int cpair = ni * 32 + j * 4 + tig;
                float2 v0 = *(const float2*)(z0 + (size_t)(row0 + row) * 256 + col);
                float2 v1 = *(const float2*)(z0 + (size_t)(row0 + row + 8) * 256 + col);
                zptr[(i * 8 + j) * 32] = make_float4(v0.x, v0.y, v1.x, v1.y);
                zh_store_pair(ZB, row, cpair, pack_h2(v0.x, v0.y));
                zh_store_pair(ZB, row + 8, cpair, pack_h2(v1.x, v1.y));
            }
    }
    __syncthreads();

    if (w == 16) {
        // ---- producer: 25 steps x 16 chunks (W1 slabs 0-7 then W2 slabs 8-15) ----
        if (lane == 0) {
            uint32_t es = 0, ep = 1;
            for (int i = 0; i < 400; i++) {
                WAITPR(sb + 64u + 16u * es, ep);
                MB_TX(sb + 16u * es, CH_BYTES);
                bulk_g2s(sb + OFF_RING + es * CH_BYTES, g_wblk + (i & 15) * CH_U2,
                         CH_BYTES, sb + 16u * es);
                es++; if (es == NSTAGE) { es = 0; ep ^= 1; }
            }
        }
        return;
    }

    // ---- compute warps ----
    const float dt = sT[1] - sT[0];
    uint32_t cs = 0, cp = 0;
    float d[2][8][4];

    for (int s = 0; s < 25; s++) {
        const float t = sT[s];
        // ---- GEMM1: D = z @ W1 (reads Z) ----
#pragma unroll
        for (int i = 0; i < 2; i++)
#pragma unroll
            for (int j = 0; j < 8; j++)
#pragma unroll
                for (int r = 0; r < 4; r++) d[i][j][r] = 0.0f;
        gemm_pass(d, smem, sb, OFF_Z, mi, ni, lane, cs, cp);
        // ---- h = tanh(D + b1 + t*wt) -> H (packed f16x2 tanh; no barrier: H != Z) ----
#pragma unroll
        for (int i = 0; i < 2; i++)
#pragma unroll
            for (int j = 0; j < 8; j++) {
                const int col = ni * 64 + j * 8 + 2 * tig;
                const int cpair = ni * 32 + j * 4 + tig;
                const float2 bw0 = sBW[col], bw1 = sBW[col + 1];
                const int row = mi * 32 + i * 16 + gid;
                float x0 = d[i][j][0] + bw0.x + t * bw0.y;
                float x1 = d[i][j][1] + bw1.x + t * bw1.y;
                zh_store_pair(HB, row, cpair, tanh_h2(pack_h2(x0, x1)));
                float x2 = d[i][j][2] + bw0.x + t * bw0.y;
                float x3 = d[i][j][3] + bw1.x + t * bw1.y;
                zh_store_pair(HB, row + 8, cpair, tanh_h2(pack_h2(x2, x3)));
            }
        BAR1();  // H fully written (also implies all Z reads done)
        // ---- GEMM2: D = h @ W2 (reads H) ----
#pragma unroll
        for (int i = 0; i < 2; i++)
#pragma unroll
            for (int j = 0; j < 8; j++)
#pragma unroll
                for (int r = 0; r < 4; r++) d[i][j][r] = 0.0f;
        gemm_pass(d, smem, sb, OFF_H, mi, ni, lane, cs, cp);
        // ---- z update: z += dt*(D + b2); master in g_z (coalesced), fp16 image -> Z ----
        const bool last = (s == 24);
#pragma unroll
        for (int i = 0; i < 2; i++)
#pragma unroll
            for (int j = 0; j < 8; j++) {
                const int col = ni * 64 + j * 8 + 2 * tig;
                const int cpair = ni * 32 + j * 4 + tig;
                const int row = mi * 32 + i * 16 + gid;
                const float bc0 = sB2[col], bc1 = sB2[col + 1];
                float4 zo = zptr[(i * 8 + j) * 32];
                float4 zn;
                zn.x = fmaf(dt, d[i][j][0] + bc0, zo.x);
                zn.y = fmaf(dt, d[i][j][1] + bc1, zo.y);
                zn.z = fmaf(dt, d[i][j][2] + bc0, zo.z);
                zn.w = fmaf(dt, d[i][j][3] + bc1, zo.w);
                zptr[(i * 8 + j) * 32] = zn;
                zh_store_pair(ZB, row, cpair, pack_h2(zn.x, zn.y));
                zh_store_pair(ZB, row + 8, cpair, pack_h2(zn.z, zn.w));
                if (last) {
                    *(float2*)(out + (size_t)(row0 + row) * 256 + col) = make_float2(zn.x, zn.y);
                    *(float2*)(out + (size_t)(row0 + row + 8) * 256 + col) = make_float2(zn.z, zn.w);
                }
            }
        BAR1();  // Z fully written (also implies all H reads done)
    }
}

extern "C" void kernel_launch(void* const* d_in, const int* in_sizes, int n_in,
                              void* d_out, int out_size) {
    const float* z0 = (const float*)d_in[0];
    const float* t_range = (const float*)d_in[1];
    const float* W1 = (const float*)d_in[2];
    const float* b1 = (const float*)d_in[3];
    const float* wt = (const float*)d_in[4];
    const float* W2 = (const float*)d_in[5];
    const float* b2 = (const float*)d_in[6];
    float* out = (float*)d_out;

    cudaFuncSetAttribute(ode_main, cudaFuncAttributeMaxDynamicSharedMemorySize, DYN_SMEM);
    ode_prep<<<16, 256>>>(W1, W2);
    ode_main<<<128, 544, DYN_SMEM>>>(z0, t_range, b1, wt, b2, out);
}

// round 16
// speedup vs baseline: 3.1120x; 3.1120x over previous
#include <cuda_runtime.h>
#include <stdint.h>

#define NSTAGE 4
#define CH_U2 2048u      // one 16KB chunk: [2 kt][32 nt][32 lane] uint2 (fp16 b-frags, k32 slab)
#define CH_BYTES 16384u

// dynamic smem layout (bytes)
// mbars: full[4] @ 0..64, empty[4] @ 64..128
#define OFF_CC 128u                              // cc[256] f32 = 25*dt*b2 -> 1152
#define OFF_BIAS 1152u                           // bias[25][256] f32 -> 26752
#define OFF_H 26752u                             // 128x256 fp16 comp-major = 65536 -> 92288
#define OFF_S 92288u                             // 128x256 fp16 comp-major sum -> 157824
#define OFF_RING 157824u
#define DYN_SMEM (OFF_RING + NSTAGE * CH_BYTES)  // 223360

// prep outputs
__device__ __align__(128) uint2 g_wblk[24 * CH_U2];  // chunks: W1 0-7, M' 8-15, W2' 16-23
__device__ __align__(16) float g_M[256 * 256];       // M' = dt * (W2 @ W1), fp32
__device__ __align__(16) float g_bias[25 * 256];     // B_s = b1 + s*c' + t_s*wt

// ---------- helpers ----------
__device__ __forceinline__ uint32_t smem_u32(const void* p) {
    uint32_t a;
    asm("{ .reg .u64 t; cvta.to.shared.u64 t, %1; cvt.u32.u64 %0, t; }" : "=r"(a) : "l"(p));
    return a;
}
__device__ __forceinline__ uint32_t pack_h2(float lo, float hi) {
    uint32_t r;
    asm("cvt.rn.f16x2.f32 %0, %1, %2;" : "=r"(r) : "f"(hi), "f"(lo));
    return r;
}
__device__ __forceinline__ uint32_t tanh_h2(uint32_t x) {
    uint32_t r;
    asm("tanh.approx.f16x2 %0, %1;" : "=r"(r) : "r"(x));
    return r;
}
__device__ __forceinline__ uint32_t hadd2(uint32_t a, uint32_t b) {
    uint32_t r;
    asm("add.rn.f16x2 %0, %1, %2;" : "=r"(r) : "r"(a), "r"(b));
    return r;
}

#define MBINIT(addr, cnt) \
    asm volatile("mbarrier.init.shared.b64 [%0], %1;" :: "r"(addr), "r"(cnt) : "memory")
#define MB_TX(addr, bytes) \
    asm volatile("mbarrier.arrive.expect_tx.shared.b64 _, [%0], %1;" :: "r"(addr), "r"(bytes) : "memory")
#define MB_ARRIVE(addr) \
    asm volatile("mbarrier.arrive.shared.b64 _, [%0];" :: "r"(addr) : "memory")

#define WAITP(addr, par) do { \
    uint32_t _m = (addr), _p = (par), _d; \
    asm volatile("{\n\t.reg .pred p;\n\t" \
        "mbarrier.try_wait.parity.acquire.cta.shared::cta.b64 p, [%1], %2;\n\t" \
        "selp.b32 %0, 1, 0, p;\n\t}" : "=r"(_d) : "r"(_m), "r"(_p) : "memory"); \
    if (!_d) { \
        asm volatile("{\n\t.reg .pred P1;\n\t" \
            "WL_%=:\n\t" \
            "mbarrier.try_wait.parity.acquire.cta.shared::cta.b64 P1, [%0], %1, 0x989680;\n\t" \
            "@P1 bra.uni WD_%=;\n\tbra.uni WL_%=;\n\tWD_%=:\n\t}" \
            :: "r"(_m), "r"(_p) : "memory"); \
    } \
} while (0)

#define WAITPR(addr, par) do { \
    uint32_t _m = (addr), _p = (par), _d; \
    asm volatile("{\n\t.reg .pred p;\n\t" \
        "mbarrier.try_wait.parity.relaxed.cta.shared::cta.b64 p, [%1], %2, 0x989680;\n\t" \
        "selp.b32 %0, 1, 0, p;\n\t}" : "=r"(_d) : "r"(_m), "r"(_p) : "memory"); \
    if (!_d) { \
        asm volatile("{\n\t.reg .pred P1;\n\t" \
            "WL_%=:\n\t" \
            "mbarrier.try_wait.parity.relaxed.cta.shared::cta.b64 P1, [%0], %1, 0x989680;\n\t" \
            "@P1 bra.uni WD_%=;\n\tbra.uni WL_%=;\n\tWD_%=:\n\t}" \
            :: "r"(_m), "r"(_p) : "memory"); \
    } \
} while (0)

#define BAR1() asm volatile("bar.sync 1, 512;" ::: "memory")

__device__ __forceinline__ void bulk_g2s(uint32_t dst, const void* src, uint32_t bytes, uint32_t mbar) {
    asm volatile(
        "cp.async.bulk.shared::cluster.global.mbarrier::complete_tx::bytes [%0], [%1], %2, [%3];"
        :: "r"(dst), "l"(src), "r"(bytes), "r"(mbar) : "memory");
}

// mma.sync m16n8k16 f16->f32 (g=lane>>2, t=lane&3):
// a0=(g,2t:2t+1) a1=(g+8,2t:2t+1) a2=(g,2t+8:2t+9) a3=(g+8,2t+8:2t+9)
// b0=(2t:2t+1, g) b1=(2t+8:2t+9, g); c0=(g,2t) c1=(g,2t+1) c2=(g+8,2t) c3=(g+8,2t+1)
#define MMA16(d, ax, ay, az, aw, bx, by) \
    asm volatile("mma.sync.aligned.m16n8k16.row.col.f32.f16.f16.f32 " \
        "{%0,%1,%2,%3}, {%4,%5,%6,%7}, {%8,%9}, {%0,%1,%2,%3};" \
        : "+f"((d)[0]), "+f"((d)[1]), "+f"((d)[2]), "+f"((d)[3]) \
        : "r"(ax), "r"(ay), "r"(az), "r"(aw), "r"(bx), "r"(by))

// comp-major A-fragment layout: (row 0..127, colpair 0..127) in 16x8cp tiles.
__device__ __forceinline__ uint32_t zh_word(int row, int cp) {
    int tile = ((row >> 4) << 4) + (cp >> 3);
    int comp = ((row >> 3) & 1) + (((cp >> 2) & 1) << 1);
    int ln = ((row & 7) << 2) + (cp & 3);
    return (uint32_t)(tile * 128 + comp * 32 + ln);
}
__device__ __forceinline__ void zh_store_pair(uint32_t* ZB, int row, int cp, uint32_t v) {
    ZB[zh_word(row, cp)] = v;
}
__device__ __forceinline__ void s_accum(uint32_t* SB, int row, int cp, uint32_t h) {
    uint32_t idx = zh_word(row, cp);
    SB[idx] = hadd2(SB[idx], h);
}

// ---------- prep 1: M' = dt*(W2 @ W1), fp32 ----------
extern "C" __global__ void __launch_bounds__(256) ode_prep_mm(
    const float* __restrict__ W1, const float* __restrict__ W2,
    const float* __restrict__ t_range) {
    int k = blockIdx.x, n = threadIdx.x;
    float dt = t_range[1] - t_range[0];
    float s = 0.0f;
    for (int j = 0; j < 256; j++) s = fmaf(W2[k * 256 + j], W1[j * 256 + n], s);
    g_M[k * 256 + n] = dt * s;
}

// ---------- prep 2: bias table B_s = b1 + s*c' + t_s*wt, c' = dt*(b2@W1) ----------
extern "C" __global__ void __launch_bounds__(256) ode_prep_bias(
    const float* __restrict__ W1, const float* __restrict__ b1,
    const float* __restrict__ wt, const float* __restrict__ b2,
    const float* __restrict__ t_range) {
    int s = blockIdx.x, n = threadIdx.x;
    float dt = t_range[1] - t_range[0];
    float c = 0.0f;
    for (int j = 0; j < 256; j++) c = fmaf(b2[j], W1[j * 256 + n], c);
    c *= dt;
    g_bias[s * 256 + n] = b1[n] + s * c + t_range[s] * wt[n];
}

// ---------- prep 3: pack fp16 b-frag k32-slab chunk images ----------
// chunk c = mat*8 + slab; sources: mat0 = W1, mat1 = g_M (dt-scaled), mat2 = dt*W2.
extern "C" __global__ void __launch_bounds__(256) ode_prep_pack(
    const float* __restrict__ W1, const float* __restrict__ W2,
    const float* __restrict__ t_range) {
    int c = blockIdx.x, mat = c >> 3, slab = c & 7;
    float dt = t_range[1] - t_range[0];
    const float* src = (mat == 0) ? W1 : (mat == 1 ? g_M : W2);
    float scl = (mat == 2) ? dt : 1.0f;
    for (int e = threadIdx.x; e < (int)CH_U2; e += 256) {
        int lane = e & 31, nt = (e >> 5) & 31, kt = e >> 10;
        int g = lane >> 2, t = lane & 3;
        int kb = slab * 32 + kt * 16, n = nt * 8 + g;
        uint2 v;
        v.x = pack_h2(scl * src[(kb + 2 * t) * 256 + n], scl * src[(kb + 2 * t + 1) * 256 + n]);
        v.y = pack_h2(scl * src[(kb + 2 * t + 8) * 256 + n], scl * src[(kb + 2 * t + 9) * 256 + n]);
        g_wblk[c * CH_U2 + e] = v;
    }
}

// ---------- GEMM pass: d += A(src buf) @ B(ring), k=256 over 8 k32 chunks ----------
__device__ __forceinline__ void gemm_pass(
    float (&d)[2][8][4], const char* smem, uint32_t sb, uint32_t a_off,
    int mi, int ni, int lane, uint32_t& cs, uint32_t& cp) {
    const uint32_t* A = (const uint32_t*)(smem + a_off);
    for (int kc = 0; kc < 8; kc++) {
        WAITP(sb + 16u * cs, cp);
        const uint2* Bk = (const uint2*)(smem + OFF_RING + cs * CH_BYTES);
#pragma unroll
        for (int kt = 0; kt < 2; kt++) {
            const int ktile = kc * 2 + kt;
            uint32_t a[2][4];
#pragma unroll
            for (int i = 0; i < 2; i++) {
                const uint32_t* Ab = A + (((mi * 2 + i) * 16 + ktile) * 128) + lane;
                a[i][0] = Ab[0]; a[i][1] = Ab[32]; a[i][2] = Ab[64]; a[i][3] = Ab[96];
            }
            uint2 b[8];
#pragma unroll
            for (int j = 0; j < 8; j++) b[j] = Bk[(kt * 32 + ni * 8 + j) * 32 + lane];
#pragma unroll
            for (int i = 0; i < 2; i++)
#pragma unroll
                for (int j = 0; j < 8; j++)
                    MMA16(d[i][j], a[i][0], a[i][1], a[i][2], a[i][3], b[j].x, b[j].y);
        }
        if (lane == 0) MB_ARRIVE(sb + 64u + 16u * cs);
        cs++; if (cs == NSTAGE) { cs = 0; cp ^= 1; }
    }
}

// ---------- main persistent kernel ----------
// u-space recurrence: u lives in accumulator registers for all 25 steps.
// GEMM0: u0 = z0@W1. Per step: h=tanh(u+B_s)->H, S+=h; u += h@M'. Final: zT = z0 + S@(dtW2) + cc.
extern "C" __global__ void __launch_bounds__(544, 1) ode_main(
    const float* __restrict__ z0, const float* __restrict__ t_range,
    const float* __restrict__ b2, float* __restrict__ out) {
    extern __shared__ char smem[];
    const uint32_t sb = smem_u32(smem);
    const int tid = threadIdx.x, w = tid >> 5, lane = tid & 31;
    const int row0 = blockIdx.x * 128;

    uint32_t* HB = (uint32_t*)(smem + OFF_H);
    uint32_t* SB = (uint32_t*)(smem + OFF_S);
    float* sCC = (float*)(smem + OFF_CC);
    float* sBias = (float*)(smem + OFF_BIAS);

    const int mi = w >> 2, ni = w & 3;  // warp tile: rows [mi*32,+32), cols [ni*64,+64)
    const int gid = lane >> 2, tig = lane & 3;

    if (tid == 0) {
        for (int s = 0; s < NSTAGE; s++) {
            MBINIT(sb + 16u * s, 1);         // full
            MBINIT(sb + 64u + 16u * s, 16);  // empty (16 compute warps)
        }
    }
    {
        float dt = t_range[1] - t_range[0];
        if (tid < 256) sCC[tid] = 25.0f * dt * b2[tid];
        for (int i = tid; i < 6400; i += 544) sBias[i] = g_bias[i];
        for (int i = tid; i < 16384; i += 544) SB[i] = 0u;
    }
    // per-warp init: z0 fragments -> fp16 image in H (A operand of GEMM0)
    if (w < 16) {
#pragma unroll
        for (int i = 0; i < 2; i++)
#pragma unroll
            for (int j = 0; j < 8; j++) {
                const int row = mi * 32 + i * 16 + gid;
                const int col = ni * 64 + j * 8 + 2 * tig;
                const int cpair = ni * 32 + j * 4 + tig;
                float2 v0 = *(const float2*)(z0 + (size_t)(row0 + row) * 256 + col);
                float2 v1 = *(const float2*)(z0 + (size_t)(row0 + row + 8) * 256 + col);
                zh_store_pair(HB, row, cpair, pack_h2(v0.x, v0.y));
                zh_store_pair(HB, row + 8, cpair, pack_h2(v1.x, v1.y));
            }
    }
    __syncthreads();

    if (w == 16) {
        // ---- producer: 216 chunks = W1 x8, (M' x8) x25, W2' x8 ----
        if (lane == 0) {
            uint32_t es = 0, ep = 1;
            for (int i = 0; i < 216; i++) {
                int chunk = (i < 8) ? i : (i < 208 ? 8 + ((i - 8) & 7) : 16 + (i - 208));
                WAITPR(sb + 64u + 16u * es, ep);
                MB_TX(sb + 16u * es, CH_BYTES);
                bulk_g2s(sb + OFF_RING + es * CH_BYTES, g_wblk + chunk * CH_U2,
                         CH_BYTES, sb + 16u * es);
                es++; if (es == NSTAGE) { es = 0; ep ^= 1; }
            }
        }
        return;
    }

    // ---- compute warps ----
    uint32_t cs = 0, cp = 0;
    float d[2][8][4];

    // GEMM0: u0 = z0 @ W1
#pragma unroll
    for (int i = 0; i < 2; i++)
#pragma unroll
        for (int j = 0; j < 8; j++)
#pragma unroll
            for (int r = 0; r < 4; r++) d[i][j][r] = 0.0f;
    gemm_pass(d, smem, sb, OFF_H, mi, ni, lane, cs, cp);

    for (int s = 0; s < 25; s++) {
        BAR1();  // all warps done reading H (z0 or previous h)
        // ---- h = tanh(u + B_s) -> H; S += h ----
        const float2* Bs = (const float2*)(smem + OFF_BIAS + (uint32_t)s * 1024u);
#pragma unroll
        for (int i = 0; i < 2; i++)
#pragma unroll
            for (int j = 0; j < 8; j++) {
                const int col = ni * 64 + j * 8 + 2 * tig;
                const int cpair = ni * 32 + j * 4 + tig;
                const int row = mi * 32 + i * 16 + gid;
                const float2 bw = Bs[col >> 1];
                uint32_t h01 = tanh_h2(pack_h2(d[i][j][0] + bw.x, d[i][j][1] + bw.y));
                zh_store_pair(HB, row, cpair, h01);
                s_accum(SB, row, cpair, h01);
                uint32_t h23 = tanh_h2(pack_h2(d[i][j][2] + bw.x, d[i][j][3] + bw.y));
                zh_store_pair(HB, row + 8, cpair, h23);
                s_accum(SB, row + 8, cpair, h23);
            }
        BAR1();  // H (and S for last iter) fully written
        // ---- u += h @ M' ----
        gemm_pass(d, smem, sb, OFF_H, mi, ni, lane, cs, cp);
    }
    BAR1();  // all warps done with last MMA (H reads finished; S complete)

    // ---- final: d = S @ (dt*W2) ----
#pragma unroll
    for (int i = 0; i < 2; i++)
#pragma unroll
        for (int j = 0; j < 8; j++)
#pragma unroll
            for (int r = 0; r < 4; r++) d[i][j][r] = 0.0f;
    gemm_pass(d, smem, sb, OFF_S, mi, ni, lane, cs, cp);

    // ---- output: zT = z0 + d + cc ----
#pragma unroll
    for (int i = 0; i < 2; i++)
#pragma unroll
        for (int j = 0; j < 8; j++) {
            const int col = ni * 64 + j * 8 + 2 * tig;
            const int row = mi * 32 + i * 16 + gid;
            const float c0 = sCC[col], c1 = sCC[col + 1];
            float2 v0 = *(const float2*)(z0 + (size_t)(row0 + row) * 256 + col);
            float2 v1 = *(const float2*)(z0 + (size_t)(row0 + row + 8) * 256 + col);
            *(float2*)(out + (size_t)(row0 + row) * 256 + col) =
                make_float2(v0.x + d[i][j][0] + c0, v0.y + d[i][j][1] + c1);
            *(float2*)(out + (size_t)(row0 + row + 8) * 256 + col) =
                make_float2(v1.x + d[i][j][2] + c0, v1.y + d[i][j][3] + c1);
        }
}

extern "C" void kernel_launch(void* const* d_in, const int* in_sizes, int n_in,
                              void* d_out, int out_size) {
    const float* z0 = (const float*)d_in[0];
    const float* t_range = (const float*)d_in[1];
    const float* W1 = (const float*)d_in[2];
    const float* b1 = (const float*)d_in[3];
    const float* wt = (const float*)d_in[4];
    const float* W2 = (const float*)d_in[5];
    const float* b2 = (const float*)d_in[6];
    float* out = (float*)d_out;

    cudaFuncSetAttribute(ode_main, cudaFuncAttributeMaxDynamicSharedMemorySize, DYN_SMEM);
    ode_prep_mm<<<256, 256>>>(W1, W2, t_range);
    ode_prep_bias<<<25, 256>>>(W1, b1, wt, b2, t_range);
    ode_prep_pack<<<24, 256>>>(W1, W2, t_range);
    ode_main<<<128, 544, DYN_SMEM>>>(z0, t_range, b2, out);
}